// round 16
// baseline (speedup 1.0000x reference)
#include <cuda_runtime.h>
#include <cstdint>

// CostVolume via single tf32 GEMM (mma.sync.m16n8k8.tf32; tcgen05 unavailable
// under virtual arch compute_103).
//
// out[b,h,j,i] = (1/128) * sum_c L[b,h,j,c]*R[b,h,j-i,c], j>=i else 0.
// Per CTA (bh, kt): D[m<128][n<64] = sum_c L[kt*64+m][c]*R[kt*64+n][c];
// out(j=kt*64+m, i=m-n) valid iff 0<=i<64; covered exactly once.
//
// Structure = round-11 optimum + dead-warp B prefetch:
//  - 2 sequential half-K phases reusing one 60KB smem buffer -> 3 CTAs/SM.
//  - A via cp.async (raw f32 bits; tf32 HMMA truncates, noise cancels over K).
//  - Phase-0 B via LDG+cvt.rna+STS.128 by all threads (LDGs issued first).
//  - Band-dead warps (wid 3,4: no valid outputs) prefetch phase-1 B into
//    registers DURING phase-0 compute (LDG latency hidden), then cvt+STS it
//    after the drain barrier -> phase-1 critical path has no B LDG chain.
//    They also write the kt==0 j<i zero region.
//
// Channel-permutation trick: K-sum invariant under channel permutations
// applied identically to A and B -> natural k-contiguous smem layout;
// LDS.128 elements .x/.y feed k-step 2t (cols c/c+4), .z/.w feed 2t+1.
// Row stride 80 floats: conflict-free LDS.128/STS.128 phases.
// lds128 volatile+memory-clobber (addresses repeat across halves).

#define WW 320
#define CC 128
#define DD 64
#define RSF 80
#define OFF_A 0
#define OFF_B (128 * RSF * 4)               // 40960
#define SMEM_TOTAL (OFF_B + 64 * RSF * 4)   // 61440
#define ROWB (RSF * 4)                      // 320 bytes per row

__device__ __forceinline__ uint32_t smem_u32(const void* p) {
    uint32_t a;
    asm("{ .reg .u64 t; cvta.to.shared.u64 t, %1; cvt.u32.u64 %0, t; }" : "=r"(a) : "l"(p));
    return a;
}
__device__ __forceinline__ uint32_t f2tf32(float x) {
    uint32_t r;
    asm("cvt.rna.tf32.f32 %0, %1;" : "=r"(r) : "f"(x));
    return r;
}
__device__ __forceinline__ void cpasync16(uint32_t dst, const void* src) {
    asm volatile("cp.async.ca.shared.global [%0], [%1], 16;"
                 :: "r"(dst), "l"(src) : "memory");
}
__device__ __forceinline__ void sts128(uint32_t addr, uint32_t x, uint32_t y,
                                       uint32_t z, uint32_t w) {
    asm volatile("st.shared.v4.b32 [%0], {%1,%2,%3,%4};"
                 :: "r"(addr), "r"(x), "r"(y), "r"(z), "r"(w) : "memory");
}
__device__ __forceinline__ uint4 lds128(uint32_t addr) {
    uint4 v;
    asm volatile("ld.shared.v4.b32 {%0,%1,%2,%3}, [%4];"
                 : "=r"(v.x), "=r"(v.y), "=r"(v.z), "=r"(v.w)
                 : "r"(addr) : "memory");
    return v;
}
__device__ __forceinline__ void mma_tf32(float* d, uint32_t a0, uint32_t a1,
                                         uint32_t a2, uint32_t a3,
                                         uint32_t b0, uint32_t b1) {
    asm volatile(
        "mma.sync.aligned.m16n8k8.row.col.f32.tf32.tf32.f32 "
        "{%0,%1,%2,%3}, {%4,%5,%6,%7}, {%8,%9}, {%0,%1,%2,%3};"
        : "+f"(d[0]), "+f"(d[1]), "+f"(d[2]), "+f"(d[3])
        : "r"(a0), "r"(a1), "r"(a2), "r"(a3), "r"(b0), "r"(b1));
}

__global__ __launch_bounds__(256, 3)
void cv_tf32_kernel(const float* __restrict__ L, const float* __restrict__ R,
                    float* __restrict__ out) {
    extern __shared__ char smem[];
    const uint32_t sb = smem_u32(smem);
    const int tid = threadIdx.x;
    const int wid = tid >> 5;
    const int lid = tid & 31;
    const int kt = blockIdx.x;      // 0..4
    const int bh = blockIdx.y;      // 0..1279

    const float* Lg = L + (size_t)bh * WW * CC;
    const float* Rg = R + (size_t)bh * WW * CC;
    float* og = out + (size_t)bh * WW * DD;

    const int wm = wid & 3;
    const int wn = wid >> 2;
    const bool work = (wid != 3) && (wid != 4);   // band-dead warps
    const int lr = lid >> 2;
    const int lc = lid & 3;
    const uint32_t aBase = sb + OFF_A + (uint32_t)((wm * 32 + lr) * ROWB + lc * 16);
    const uint32_t bBase = sb + OFF_B + (uint32_t)((wn * 32 + lr) * ROWB + lc * 16);
    const uint32_t R8 = 8 * ROWB;   // 2560

    const int g  = tid & 15;        // A/B0: 16B chunk (channels 4g..4g+3 of half)
    const int m0 = tid >> 4;        // A/B0: starting row, stride 16

    // dead-warp B1 prefetch mapping: dt=tid-96 in [0,64); chunk q, rows nr+4k
    const int dt = tid - 96;
    const int q  = dt & 15;
    const int nr = dt >> 4;
    float4 bv[16];

    float acc[2][4][4];
    #pragma unroll
    for (int mf = 0; mf < 2; mf++)
        #pragma unroll
        for (int nf = 0; nf < 4; nf++)
            #pragma unroll
            for (int c = 0; c < 4; c++) acc[mf][nf][c] = 0.f;

    // ================= phase 0 =================
    {
        // B0 LDGs first (longest latency starts earliest)
        const int csrc = g * 4;
        const float4* srcB = (const float4*)(Rg + (size_t)(kt * 64 + m0) * CC + csrc);
        float4 b0v = __ldg(srcB);
        float4 b1v = __ldg(srcB + 16 * (CC / 4));
        float4 b2v = __ldg(srcB + 32 * (CC / 4));
        float4 b3v = __ldg(srcB + 48 * (CC / 4));
        // A0 cp.async
        uint32_t dstA = sb + OFF_A + (uint32_t)(m0 * ROWB + g * 16);
        if (kt < 4) {
            const float* srcA = Lg + (size_t)(kt * 64 + m0) * CC + csrc;
            #pragma unroll
            for (int it = 0; it < 8; it++) {
                cpasync16(dstA, srcA);
                srcA += 16 * CC;
                dstA += 16 * ROWB;
            }
        } else {
            #pragma unroll
            for (int it = 0; it < 8; it++) {
                int j = 256 + m0 + it * 16;
                if (j > WW - 1) j = WW - 1;   // overrun rows pruned at store
                cpasync16(dstA, Lg + (size_t)j * CC + csrc);
                dstA += 16 * ROWB;
            }
        }
        asm volatile("cp.async.commit_group;" ::: "memory");
        // B0 cvt + STS
        uint32_t dstB = sb + OFF_B + (uint32_t)(m0 * ROWB + g * 16);
        sts128(dstB,               f2tf32(b0v.x), f2tf32(b0v.y), f2tf32(b0v.z), f2tf32(b0v.w));
        sts128(dstB + 16 * ROWB,   f2tf32(b1v.x), f2tf32(b1v.y), f2tf32(b1v.z), f2tf32(b1v.w));
        sts128(dstB + 32 * ROWB,   f2tf32(b2v.x), f2tf32(b2v.y), f2tf32(b2v.z), f2tf32(b2v.w));
        sts128(dstB + 48 * ROWB,   f2tf32(b3v.x), f2tf32(b3v.y), f2tf32(b3v.z), f2tf32(b3v.w));
        asm volatile("cp.async.wait_group 0;" ::: "memory");
    }
    __syncthreads();

    if (work) {
        #pragma unroll
        for (int t = 0; t < 4; t++) {
            const uint32_t ko = t * 64;
            uint4 a0 = lds128(aBase + ko);
            uint4 a1 = lds128(aBase + R8 + ko);
            uint4 a2 = lds128(aBase + 2 * R8 + ko);
            uint4 a3 = lds128(aBase + 3 * R8 + ko);
            uint4 b0 = lds128(bBase + ko);
            uint4 b1 = lds128(bBase + R8 + ko);
            uint4 b2 = lds128(bBase + 2 * R8 + ko);
            uint4 b3 = lds128(bBase + 3 * R8 + ko);
            mma_tf32(acc[0][0], a0.x, a1.x, a0.y, a1.y, b0.x, b0.y);
            mma_tf32(acc[0][1], a0.x, a1.x, a0.y, a1.y, b1.x, b1.y);
            mma_tf32(acc[0][2], a0.x, a1.x, a0.y, a1.y, b2.x, b2.y);
            mma_tf32(acc[0][3], a0.x, a1.x, a0.y, a1.y, b3.x, b3.y);
            mma_tf32(acc[1][0], a2.x, a3.x, a2.y, a3.y, b0.x, b0.y);
            mma_tf32(acc[1][1], a2.x, a3.x, a2.y, a3.y, b1.x, b1.y);
            mma_tf32(acc[1][2], a2.x, a3.x, a2.y, a3.y, b2.x, b2.y);
            mma_tf32(acc[1][3], a2.x, a3.x, a2.y, a3.y, b3.x, b3.y);
            mma_tf32(acc[0][0], a0.z, a1.z, a0.w, a1.w, b0.z, b0.w);
            mma_tf32(acc[0][1], a0.z, a1.z, a0.w, a1.w, b1.z, b1.w);
            mma_tf32(acc[0][2], a0.z, a1.z, a0.w, a1.w, b2.z, b2.w);
            mma_tf32(acc[0][3], a0.z, a1.z, a0.w, a1.w, b3.z, b3.w);
            mma_tf32(acc[1][0], a2.z, a3.z, a2.w, a3.w, b0.z, b0.w);
            mma_tf32(acc[1][1], a2.z, a3.z, a2.w, a3.w, b1.z, b1.w);
            mma_tf32(acc[1][2], a2.z, a3.z, a2.w, a3.w, b2.z, b2.w);
            mma_tf32(acc[1][3], a2.z, a3.z, a2.w, a3.w, b3.z, b3.w);
        }
    } else {
        // dead warps: prefetch B1 (channels 64..127) into registers; the
        // LDG latency hides under the other warps' phase-0 mainloop.
        #pragma unroll
        for (int k2 = 0; k2 < 16; k2++)
            bv[k2] = __ldg((const float4*)(Rg + (size_t)(kt * 64 + nr + 4 * k2) * CC + 64) + q);
        if (kt == 0) {
            int j = dt;             // 0..63: j<i zero region
            for (int i = j + 1; i < 64; i++)
                og[(size_t)j * DD + i] = 0.f;
        }
    }

    // ================= phase 1 =================
    __syncthreads();                // drain readers before overwriting smem
    {
        const int csrc = 64 + g * 4;
        uint32_t dstA = sb + OFF_A + (uint32_t)(m0 * ROWB + g * 16);
        if (kt < 4) {
            const float* srcA = Lg + (size_t)(kt * 64 + m0) * CC + csrc;
            #pragma unroll
            for (int it = 0; it < 8; it++) {
                cpasync16(dstA, srcA);
                srcA += 16 * CC;
                dstA += 16 * ROWB;
            }
        } else {
            #pragma unroll
            for (int it = 0; it < 8; it++) {
                int j = 256 + m0 + it * 16;
                if (j > WW - 1) j = WW - 1;
                cpasync16(dstA, Lg + (size_t)j * CC + csrc);
                dstA += 16 * ROWB;
            }
        }
        asm volatile("cp.async.commit_group;" ::: "memory");
        if (!work) {
            // B1 from prefetched registers: cvt + conflict-free STS.128
            #pragma unroll
            for (int k2 = 0; k2 < 16; k2++) {
                uint32_t d = sb + OFF_B + (uint32_t)((nr + 4 * k2) * ROWB + q * 16);
                sts128(d, f2tf32(bv[k2].x), f2tf32(bv[k2].y),
                          f2tf32(bv[k2].z), f2tf32(bv[k2].w));
            }
        }
        asm volatile("cp.async.wait_group 0;" ::: "memory");
    }
    __syncthreads();

    if (work) {
        #pragma unroll
        for (int t = 0; t < 4; t++) {
            const uint32_t ko = t * 64;
            uint4 a0 = lds128(aBase + ko);
            uint4 a1 = lds128(aBase + R8 + ko);
            uint4 a2 = lds128(aBase + 2 * R8 + ko);
            uint4 a3 = lds128(aBase + 3 * R8 + ko);
            uint4 b0 = lds128(bBase + ko);
            uint4 b1 = lds128(bBase + R8 + ko);
            uint4 b2 = lds128(bBase + 2 * R8 + ko);
            uint4 b3 = lds128(bBase + 3 * R8 + ko);
            mma_tf32(acc[0][0], a0.x, a1.x, a0.y, a1.y, b0.x, b0.y);
            mma_tf32(acc[0][1], a0.x, a1.x, a0.y, a1.y, b1.x, b1.y);
            mma_tf32(acc[0][2], a0.x, a1.x, a0.y, a1.y, b2.x, b2.y);
            mma_tf32(acc[0][3], a0.x, a1.x, a0.y, a1.y, b3.x, b3.y);
            mma_tf32(acc[1][0], a2.x, a3.x, a2.y, a3.y, b0.x, b0.y);
            mma_tf32(acc[1][1], a2.x, a3.x, a2.y, a3.y, b1.x, b1.y);
            mma_tf32(acc[1][2], a2.x, a3.x, a2.y, a3.y, b2.x, b2.y);
            mma_tf32(acc[1][3], a2.x, a3.x, a2.y, a3.y, b3.x, b3.y);
            mma_tf32(acc[0][0], a0.z, a1.z, a0.w, a1.w, b0.z, b0.w);
            mma_tf32(acc[0][1], a0.z, a1.z, a0.w, a1.w, b1.z, b1.w);
            mma_tf32(acc[0][2], a0.z, a1.z, a0.w, a1.w, b2.z, b2.w);
            mma_tf32(acc[0][3], a0.z, a1.z, a0.w, a1.w, b3.z, b3.w);
            mma_tf32(acc[1][0], a2.z, a3.z, a2.w, a3.w, b0.z, b0.w);
            mma_tf32(acc[1][1], a2.z, a3.z, a2.w, a3.w, b1.z, b1.w);
            mma_tf32(acc[1][2], a2.z, a3.z, a2.w, a3.w, b2.z, b2.w);
            mma_tf32(acc[1][3], a2.z, a3.z, a2.w, a3.w, b3.z, b3.w);
        }
    }

    // ---- Epilogue: direct predicated stores (L2 merges spans) ----
    if (work) {
        const float inv = 1.0f / 128.0f;
        const int mrow = wm * 32 + lr;
        const int ncol = wn * 32 + lc * 2;
        const int jrow = kt * 64 + mrow;
        #pragma unroll
        for (int mf = 0; mf < 2; mf++) {
            #pragma unroll
            for (int c2 = 0; c2 < 2; c2++) {
                int j = jrow + mf * 16 + c2 * 8;
                if (j >= WW) continue;
                int m = j - kt * 64;
                float* orow = og + (size_t)j * DD;
                #pragma unroll
                for (int nf = 0; nf < 4; nf++) {
                    #pragma unroll
                    for (int c1 = 0; c1 < 2; c1++) {
                        int n = ncol + nf * 8 + c1;
                        int i = m - n;
                        if (i >= 0 && i < 64)
                            orow[i] = acc[mf][nf][c2 * 2 + c1] * inv;
                    }
                }
            }
        }
    }
}

extern "C" void kernel_launch(void* const* d_in, const int* in_sizes, int n_in,
                              void* d_out, int out_size) {
    const float* left  = (const float*)d_in[0];
    const float* right = (const float*)d_in[1];
    float* out = (float*)d_out;

    cudaFuncSetAttribute(cv_tf32_kernel,
                         cudaFuncAttributeMaxDynamicSharedMemorySize, SMEM_TOTAL);
    dim3 grid(5, 8 * 160);   // (kt, bh)
    cv_tf32_kernel<<<grid, 256, SMEM_TOTAL>>>(left, right, out);
}

// round 17
// speedup vs baseline: 1.2070x; 1.2070x over previous
#include <cuda_runtime.h>
#include <cstdint>

// CostVolume via single tf32 GEMM (mma.sync.m16n8k8.tf32; tcgen05 unavailable
// under virtual arch compute_103).
//
// out[b,h,j,i] = (1/128) * sum_c L[b,h,j,c]*R[b,h,j-i,c], j>=i else 0.
// Per CTA (bh, kt): D[m<128][n<64] = sum_c L[kt*64+m][c]*R[kt*64+n][c];
// out(j=kt*64+m, i=m-n) valid iff 0<=i<64; covered exactly once.
//
// This is the measured-optimal configuration (120.4us): structural variants
// (finer pipelining r12, raw-B r13, B-resident r14, dead-warp-prefetch r16)
// all regressed. Cross-CTA overlap at 3 CTAs/SM does the latency hiding.
//
// Channel-permutation trick: the K-sum is invariant under any channel
// permutation applied identically to A and B, so tiles are stored in NATURAL
// k-contiguous layout (cp.async-compatible) and the LDS.128 elements are
// re-wired to MMA columns: elements .x/.y feed k-step 2t (cols c / c+4),
// .z/.w feed k-step 2t+1. A is loaded via cp.async (raw f32 bits; HMMA
// truncates to tf32), B via LDG+cvt.rna+STS.128 (keeps rel_err ~4.6e-4).
//
// K processed in 2 sequential halves of 64 reusing one smem buffer
// (60KB/CTA -> 3 CTAs/SM). Row stride 80 floats (64 data + 16 pad):
// LDS.128 phases conflict-free (row-pair offset 80 = 16 mod 32 banks).
// Dead-warp skip: warps wid 3,4 have no valid outputs -> skip mainloop,
// handle the kt==0 j<i zero region instead.
// lds128 MUST be volatile+memory-clobber (same addresses across halves).

#define WW 320
#define CC 128
#define DD 64
#define RSF 80
#define OFF_A 0
#define OFF_B (128 * RSF * 4)               // 40960
#define SMEM_TOTAL (OFF_B + 64 * RSF * 4)   // 61440
#define ROWB (RSF * 4)                      // 320 bytes per row

__device__ __forceinline__ uint32_t smem_u32(const void* p) {
    uint32_t a;
    asm("{ .reg .u64 t; cvta.to.shared.u64 t, %1; cvt.u32.u64 %0, t; }" : "=r"(a) : "l"(p));
    return a;
}
__device__ __forceinline__ uint32_t f2tf32(float x) {
    uint32_t r;
    asm("cvt.rna.tf32.f32 %0, %1;" : "=r"(r) : "f"(x));
    return r;
}
__device__ __forceinline__ void cpasync16(uint32_t dst, const void* src) {
    asm volatile("cp.async.ca.shared.global [%0], [%1], 16;"
                 :: "r"(dst), "l"(src) : "memory");
}
__device__ __forceinline__ void sts128(uint32_t addr, uint32_t x, uint32_t y,
                                       uint32_t z, uint32_t w) {
    asm volatile("st.shared.v4.b32 [%0], {%1,%2,%3,%4};"
                 :: "r"(addr), "r"(x), "r"(y), "r"(z), "r"(w) : "memory");
}
__device__ __forceinline__ uint4 lds128(uint32_t addr) {
    uint4 v;
    asm volatile("ld.shared.v4.b32 {%0,%1,%2,%3}, [%4];"
                 : "=r"(v.x), "=r"(v.y), "=r"(v.z), "=r"(v.w)
                 : "r"(addr) : "memory");
    return v;
}
__device__ __forceinline__ void mma_tf32(float* d, uint32_t a0, uint32_t a1,
                                         uint32_t a2, uint32_t a3,
                                         uint32_t b0, uint32_t b1) {
    asm volatile(
        "mma.sync.aligned.m16n8k8.row.col.f32.tf32.tf32.f32 "
        "{%0,%1,%2,%3}, {%4,%5,%6,%7}, {%8,%9}, {%0,%1,%2,%3};"
        : "+f"(d[0]), "+f"(d[1]), "+f"(d[2]), "+f"(d[3])
        : "r"(a0), "r"(a1), "r"(a2), "r"(a3), "r"(b0), "r"(b1));
}

__global__ __launch_bounds__(256, 3)
void cv_tf32_kernel(const float* __restrict__ L, const float* __restrict__ R,
                    float* __restrict__ out) {
    extern __shared__ char smem[];
    const uint32_t sb = smem_u32(smem);
    const int tid = threadIdx.x;
    const int wid = tid >> 5;
    const int lid = tid & 31;
    const int kt = blockIdx.x;      // 0..4
    const int bh = blockIdx.y;      // 0..1279

    const float* Lg = L + (size_t)bh * WW * CC;
    const float* Rg = R + (size_t)bh * WW * CC;
    float* og = out + (size_t)bh * WW * DD;

    const int wm = wid & 3;
    const int wn = wid >> 2;
    const bool work = (wid != 3) && (wid != 4);   // band-dead warps
    const int lr = lid >> 2;
    const int lc = lid & 3;
    const uint32_t aBase = sb + OFF_A + (uint32_t)((wm * 32 + lr) * ROWB + lc * 16);
    const uint32_t bBase = sb + OFF_B + (uint32_t)((wn * 32 + lr) * ROWB + lc * 16);
    const uint32_t R8 = 8 * ROWB;   // 2560

    const int g  = tid & 15;        // 16B chunk: channels 4g..4g+3 of the half
    const int m0 = tid >> 4;        // starting row, stride 16

    float acc[2][4][4];
    #pragma unroll
    for (int mf = 0; mf < 2; mf++)
        #pragma unroll
        for (int nf = 0; nf < 4; nf++)
            #pragma unroll
            for (int c = 0; c < 4; c++) acc[mf][nf][c] = 0.f;

    #pragma unroll
    for (int kh = 0; kh < 2; kh++) {
        if (kh) __syncthreads();    // drain readers before overwriting smem

        // ---- Prologue: A via cp.async (raw f32), B via LDG+cvt.rna+STS.128 ----
        {
            const int csrc = kh * 64 + g * 4;
            // A: 8 x cp.async, rows m0+16it (clamped at 319)
            uint32_t dstA = sb + OFF_A + (uint32_t)(m0 * ROWB + g * 16);
            #pragma unroll
            for (int it = 0; it < 8; it++) {
                int j = kt * 64 + m0 + it * 16;
                if (j > WW - 1) j = WW - 1;     // overrun rows pruned at store
                cpasync16(dstA, Lg + (size_t)j * CC + csrc);
                dstA += 16 * ROWB;
            }
            asm volatile("cp.async.commit_group;" ::: "memory");
            // B: LDG.128 -> cvt.rna x4 -> STS.128 (overlaps with async copies)
            uint32_t dstB = sb + OFF_B + (uint32_t)(m0 * ROWB + g * 16);
            const float4* srcB = (const float4*)(Rg + (size_t)(kt * 64 + m0) * CC + csrc);
            #pragma unroll
            for (int it = 0; it < 4; it++) {
                float4 v = __ldg(srcB);
                sts128(dstB, f2tf32(v.x), f2tf32(v.y), f2tf32(v.z), f2tf32(v.w));
                srcB += 16 * (CC / 4);
                dstB += 16 * ROWB;
            }
            asm volatile("cp.async.wait_group 0;" ::: "memory");
        }
        __syncthreads();

        if (work) {
            // ---- Mainloop: warp tile 32x32, 4 t-iters per half ----
            // LDS.128 elements: .x/.y -> k-step 2t (cols c/c+4), .z/.w -> 2t+1.
            #pragma unroll
            for (int t = 0; t < 4; t++) {
                const uint32_t ko = t * 64;
                uint4 a0 = lds128(aBase + ko);
                uint4 a1 = lds128(aBase + R8 + ko);
                uint4 a2 = lds128(aBase + 2 * R8 + ko);
                uint4 a3 = lds128(aBase + 3 * R8 + ko);
                uint4 b0 = lds128(bBase + ko);
                uint4 b1 = lds128(bBase + R8 + ko);
                uint4 b2 = lds128(bBase + 2 * R8 + ko);
                uint4 b3 = lds128(bBase + 3 * R8 + ko);
                mma_tf32(acc[0][0], a0.x, a1.x, a0.y, a1.y, b0.x, b0.y);
                mma_tf32(acc[0][1], a0.x, a1.x, a0.y, a1.y, b1.x, b1.y);
                mma_tf32(acc[0][2], a0.x, a1.x, a0.y, a1.y, b2.x, b2.y);
                mma_tf32(acc[0][3], a0.x, a1.x, a0.y, a1.y, b3.x, b3.y);
                mma_tf32(acc[1][0], a2.x, a3.x, a2.y, a3.y, b0.x, b0.y);
                mma_tf32(acc[1][1], a2.x, a3.x, a2.y, a3.y, b1.x, b1.y);
                mma_tf32(acc[1][2], a2.x, a3.x, a2.y, a3.y, b2.x, b2.y);
                mma_tf32(acc[1][3], a2.x, a3.x, a2.y, a3.y, b3.x, b3.y);
                mma_tf32(acc[0][0], a0.z, a1.z, a0.w, a1.w, b0.z, b0.w);
                mma_tf32(acc[0][1], a0.z, a1.z, a0.w, a1.w, b1.z, b1.w);
                mma_tf32(acc[0][2], a0.z, a1.z, a0.w, a1.w, b2.z, b2.w);
                mma_tf32(acc[0][3], a0.z, a1.z, a0.w, a1.w, b3.z, b3.w);
                mma_tf32(acc[1][0], a2.z, a3.z, a2.w, a3.w, b0.z, b0.w);
                mma_tf32(acc[1][1], a2.z, a3.z, a2.w, a3.w, b1.z, b1.w);
                mma_tf32(acc[1][2], a2.z, a3.z, a2.w, a3.w, b2.z, b2.w);
                mma_tf32(acc[1][3], a2.z, a3.z, a2.w, a3.w, b3.z, b3.w);
            }
        } else if (kh == 0 && kt == 0) {
            // idle warps write the j<i zeros concurrently (disjoint addresses)
            int j = tid - 96;       // tid in [96,160) -> j 0..63
            for (int i = j + 1; i < 64; i++)
                og[(size_t)j * DD + i] = 0.f;
        }
    }

    // ---- Epilogue: direct predicated stores (L2 merges spans) ----
    if (work) {
        const float inv = 1.0f / 128.0f;
        const int mrow = wm * 32 + lr;
        const int ncol = wn * 32 + lc * 2;
        const int jrow = kt * 64 + mrow;
        #pragma unroll
        for (int mf = 0; mf < 2; mf++) {
            #pragma unroll
            for (int c2 = 0; c2 < 2; c2++) {          // c>>1: +0/+8 m rows
                int j = jrow + mf * 16 + c2 * 8;
                if (j >= WW) continue;                 // kt==4 overrun rows
                int m = j - kt * 64;
                float* orow = og + (size_t)j * DD;
                #pragma unroll
                for (int nf = 0; nf < 4; nf++) {
                    #pragma unroll
                    for (int c1 = 0; c1 < 2; c1++) {   // c&1: n parity
                        int n = ncol + nf * 8 + c1;
                        int i = m - n;
                        if (i >= 0 && i < 64)
                            orow[i] = acc[mf][nf][c2 * 2 + c1] * inv;
                    }
                }
            }
        }
    }
}

extern "C" void kernel_launch(void* const* d_in, const int* in_sizes, int n_in,
                              void* d_out, int out_size) {
    const float* left  = (const float*)d_in[0];
    const float* right = (const float*)d_in[1];
    float* out = (float*)d_out;

    cudaFuncSetAttribute(cv_tf32_kernel,
                         cudaFuncAttributeMaxDynamicSharedMemorySize, SMEM_TOTAL);
    dim3 grid(5, 8 * 160);   // (kt, bh)
    cv_tf32_kernel<<<grid, 256, SMEM_TOTAL>>>(left, right, out);
}